// round 1
// baseline (speedup 1.0000x reference)
#include <cuda_runtime.h>
#include <math_constants.h>

#define E_DIM 1024
#define BATCH 2
#define SEQ   2048
#define NHEAD 16
#define HDIM  64
#define MTOT  4096   // BATCH*SEQ

// ---------------- scratch (no allocations allowed) ----------------
__device__ float g_h   [MTOT * E_DIM];       // ln output (reused for h2)
__device__ float g_qkv [MTOT * 3 * E_DIM];   // qkv
__device__ float g_o   [MTOT * E_DIM];       // attention output
__device__ float g_x2  [MTOT * E_DIM];       // residual 1
__device__ float g_mbuf[MTOT * 4 * E_DIM];   // mlp hidden

// ---------------- layernorm ----------------
__global__ __launch_bounds__(256) void ln_kernel(const float* __restrict__ x,
                                                 float* __restrict__ y) {
    __shared__ float rs[8], rq[8];
    const int row = blockIdx.x;
    const int tid = threadIdx.x;
    const float4* xr = (const float4*)(x + (size_t)row * E_DIM);
    float4 v = xr[tid];
    float s  = v.x + v.y + v.z + v.w;
    float sq = v.x*v.x + v.y*v.y + v.z*v.z + v.w*v.w;
#pragma unroll
    for (int o = 16; o; o >>= 1) {
        s  += __shfl_xor_sync(0xffffffffu, s,  o);
        sq += __shfl_xor_sync(0xffffffffu, sq, o);
    }
    if ((tid & 31) == 0) { rs[tid >> 5] = s; rq[tid >> 5] = sq; }
    __syncthreads();
    if (tid < 32) {
        s  = (tid < 8) ? rs[tid] : 0.f;
        sq = (tid < 8) ? rq[tid] : 0.f;
#pragma unroll
        for (int o = 4; o; o >>= 1) {
            s  += __shfl_xor_sync(0xffffffffu, s,  o);
            sq += __shfl_xor_sync(0xffffffffu, sq, o);
        }
        if (tid == 0) { rs[0] = s; rq[0] = sq; }
    }
    __syncthreads();
    const float mean = rs[0] * (1.0f / E_DIM);
    const float var  = rq[0] * (1.0f / E_DIM) - mean * mean;
    const float rstd = rsqrtf(var + 1e-5f);
    float4 o4 = { (v.x - mean) * rstd, (v.y - mean) * rstd,
                  (v.z - mean) * rstd, (v.w - mean) * rstd };
    ((float4*)(y + (size_t)row * E_DIM))[tid] = o4;
}

// ---------------- GEMM: C[M,N] = A[M,K] * B[N,K]^T (+ epilogue) ----------------
// MODE 0: none   1: relu(acc+bias)   2: acc+res   3: acc+bias+res
template<int MODE>
__global__ __launch_bounds__(256) void gemm_kernel(
    const float* __restrict__ A, const float* __restrict__ Bm,
    const float* __restrict__ bias, const float* __restrict__ res,
    float* __restrict__ C, int M, int N, int K)
{
    __shared__ float As[16][128];
    __shared__ float Bs[16][128];
    const int tid  = threadIdx.x;
    const int row0 = blockIdx.y * 128;
    const int col0 = blockIdx.x * 128;
    const int tx = tid & 15, ty = tid >> 4;

    float acc[8][8];
#pragma unroll
    for (int i = 0; i < 8; i++)
#pragma unroll
        for (int j = 0; j < 8; j++) acc[i][j] = 0.f;

    const int lr = tid >> 2;        // row within tile (0..63), +64 on 2nd pass
    const int lc = (tid & 3) * 4;   // k offset (0,4,8,12)

    for (int k0 = 0; k0 < K; k0 += 16) {
#pragma unroll
        for (int i = 0; i < 2; i++) {
            const int r = lr + i * 64;
            float4 va = *(const float4*)&A [(size_t)(row0 + r) * K + k0 + lc];
            As[lc+0][r] = va.x; As[lc+1][r] = va.y; As[lc+2][r] = va.z; As[lc+3][r] = va.w;
            float4 vb = *(const float4*)&Bm[(size_t)(col0 + r) * K + k0 + lc];
            Bs[lc+0][r] = vb.x; Bs[lc+1][r] = vb.y; Bs[lc+2][r] = vb.z; Bs[lc+3][r] = vb.w;
        }
        __syncthreads();
#pragma unroll
        for (int kk = 0; kk < 16; kk++) {
            float a[8], b[8];
#pragma unroll
            for (int i = 0; i < 8; i++) a[i] = As[kk][ty * 8 + i];
#pragma unroll
            for (int j = 0; j < 8; j++) b[j] = Bs[kk][tx * 8 + j];
#pragma unroll
            for (int i = 0; i < 8; i++)
#pragma unroll
                for (int j = 0; j < 8; j++)
                    acc[i][j] = fmaf(a[i], b[j], acc[i][j]);
        }
        __syncthreads();
    }

#pragma unroll
    for (int i = 0; i < 8; i++) {
        const int r = row0 + ty * 8 + i;
#pragma unroll
        for (int j = 0; j < 8; j += 4) {
            const int c = col0 + tx * 8 + j;
            float4 v = { acc[i][j], acc[i][j+1], acc[i][j+2], acc[i][j+3] };
            if (MODE == 1 || MODE == 3) {
                v.x += bias[c]; v.y += bias[c+1]; v.z += bias[c+2]; v.w += bias[c+3];
            }
            if (MODE == 1) {
                v.x = fmaxf(v.x, 0.f); v.y = fmaxf(v.y, 0.f);
                v.z = fmaxf(v.z, 0.f); v.w = fmaxf(v.w, 0.f);
            }
            if (MODE == 2 || MODE == 3) {
                float4 rr = *(const float4*)&res[(size_t)r * N + c];
                v.x += rr.x; v.y += rr.y; v.z += rr.z; v.w += rr.w;
            }
            *(float4*)&C[(size_t)r * N + c] = v;
        }
    }
}

// ---------------- causal flash attention ----------------
#define BQ  64
#define BKV 32
__global__ __launch_bounds__(256) void attn_kernel(const float* __restrict__ qkv,
                                                   float* __restrict__ o)
{
    __shared__ float Qs[BQ][HDIM + 1];
    __shared__ float Ks[BKV][HDIM + 1];
    __shared__ float Vs[BKV][HDIM + 1];
    __shared__ float Ss[BQ][BKV + 1];
    __shared__ float m_sh[BQ], l_sh[BQ], c_sh[BQ];

    const int tid = threadIdx.x;
    const int q0  = blockIdx.x * BQ;
    const int h   = blockIdx.y;
    const int b   = blockIdx.z;
    const size_t base = (size_t)b * SEQ * 3 * E_DIM + (size_t)h * HDIM;

    // load Q tile [BQ][64]
#pragma unroll
    for (int i = 0; i < 4; i++) {
        const int f = tid + i * 256;     // 1024 float4
        const int r = f >> 4;
        const int c = (f & 15) * 4;
        float4 v = *(const float4*)&qkv[base + (size_t)(q0 + r) * 3 * E_DIM + c];
        Qs[r][c] = v.x; Qs[r][c+1] = v.y; Qs[r][c+2] = v.z; Qs[r][c+3] = v.w;
    }
    if (tid < BQ) { m_sh[tid] = -CUDART_INF_F; l_sh[tid] = 0.f; }

    const int tx = tid & 15, ty = tid >> 4;
    float oacc[4][4];
#pragma unroll
    for (int i = 0; i < 4; i++)
#pragma unroll
        for (int j = 0; j < 4; j++) oacc[i][j] = 0.f;

    const float scale = 0.125f;   // 1/sqrt(64)

    for (int k0 = 0; k0 <= q0 + BQ - 1; k0 += BKV) {
        __syncthreads();   // also covers Q load / m init on first iter
        // load K,V tiles [BKV][64]
#pragma unroll
        for (int i = 0; i < 2; i++) {
            const int f = tid + i * 256;  // 512 float4
            const int r = f >> 4;
            const int c = (f & 15) * 4;
            float4 kv = *(const float4*)&qkv[base + E_DIM     + (size_t)(k0 + r) * 3 * E_DIM + c];
            Ks[r][c] = kv.x; Ks[r][c+1] = kv.y; Ks[r][c+2] = kv.z; Ks[r][c+3] = kv.w;
            float4 vv = *(const float4*)&qkv[base + 2 * E_DIM + (size_t)(k0 + r) * 3 * E_DIM + c];
            Vs[r][c] = vv.x; Vs[r][c+1] = vv.y; Vs[r][c+2] = vv.z; Vs[r][c+3] = vv.w;
        }
        __syncthreads();

        // scores: each thread 4 rows x 2 cols of [BQ][BKV]
        float s[4][2] = {{0.f,0.f},{0.f,0.f},{0.f,0.f},{0.f,0.f}};
#pragma unroll 8
        for (int d = 0; d < HDIM; d++) {
            const float k0v = Ks[tx * 2 + 0][d];
            const float k1v = Ks[tx * 2 + 1][d];
#pragma unroll
            for (int i = 0; i < 4; i++) {
                const float q = Qs[ty * 4 + i][d];
                s[i][0] = fmaf(q, k0v, s[i][0]);
                s[i][1] = fmaf(q, k1v, s[i][1]);
            }
        }
#pragma unroll
        for (int i = 0; i < 4; i++)
#pragma unroll
            for (int j = 0; j < 2; j++) {
                const int qi = q0 + ty * 4 + i;
                const int ki = k0 + tx * 2 + j;
                Ss[ty * 4 + i][tx * 2 + j] = (ki <= qi) ? s[i][j] * scale : -CUDART_INF_F;
            }
        __syncthreads();

        // online softmax, one thread per row
        if (tid < BQ) {
            const int r = tid;
            float mx = -CUDART_INF_F;
#pragma unroll
            for (int c = 0; c < BKV; c++) mx = fmaxf(mx, Ss[r][c]);
            const float mo = m_sh[r];
            const float nm = fmaxf(mo, mx);
            const float corr = __expf(mo - nm);   // 0 on first tile
            float sum = 0.f;
#pragma unroll
            for (int c = 0; c < BKV; c++) {
                const float p = __expf(Ss[r][c] - nm);
                Ss[r][c] = p;
                sum += p;
            }
            l_sh[r] = l_sh[r] * corr + sum;
            m_sh[r] = nm;
            c_sh[r] = corr;
        }
        __syncthreads();

        // O update: each thread 4 rows x 4 d-cols
#pragma unroll
        for (int i = 0; i < 4; i++) {
            const float corr = c_sh[ty * 4 + i];
#pragma unroll
            for (int j = 0; j < 4; j++) oacc[i][j] *= corr;
        }
#pragma unroll 4
        for (int kk = 0; kk < BKV; kk++) {
            float vv[4];
#pragma unroll
            for (int j = 0; j < 4; j++) vv[j] = Vs[kk][tx * 4 + j];
#pragma unroll
            for (int i = 0; i < 4; i++) {
                const float p = Ss[ty * 4 + i][kk];
#pragma unroll
                for (int j = 0; j < 4; j++) oacc[i][j] = fmaf(p, vv[j], oacc[i][j]);
            }
        }
    }

    // write O (head-major packing back to [B,S,E])
#pragma unroll
    for (int i = 0; i < 4; i++) {
        const int r = ty * 4 + i;
        const float inv = 1.0f / l_sh[r];
        float4 v = { oacc[i][0] * inv, oacc[i][1] * inv,
                     oacc[i][2] * inv, oacc[i][3] * inv };
        *(float4*)&o[((size_t)b * SEQ + q0 + r) * E_DIM + h * HDIM + tx * 4] = v;
    }
}

// ---------------- launch ----------------
extern "C" void kernel_launch(void* const* d_in, const int* in_sizes, int n_in,
                              void* d_out, int out_size) {
    const float* x      = (const float*)d_in[0];
    const float* w_in   = (const float*)d_in[1];
    const float* w_out  = (const float*)d_in[2];
    const float* w_fc   = (const float*)d_in[3];
    const float* b_fc   = (const float*)d_in[4];
    const float* w_proj = (const float*)d_in[5];
    const float* b_proj = (const float*)d_in[6];
    float* out = (float*)d_out;

    float *h, *qkv, *o, *x2, *mb;
    cudaGetSymbolAddress((void**)&h,   g_h);
    cudaGetSymbolAddress((void**)&qkv, g_qkv);
    cudaGetSymbolAddress((void**)&o,   g_o);
    cudaGetSymbolAddress((void**)&x2,  g_x2);
    cudaGetSymbolAddress((void**)&mb,  g_mbuf);

    // h = ln(x)
    ln_kernel<<<MTOT, 256>>>(x, h);
    // qkv = h @ w_in^T
    gemm_kernel<0><<<dim3(3 * E_DIM / 128, MTOT / 128), 256>>>(
        h, w_in, nullptr, nullptr, qkv, MTOT, 3 * E_DIM, E_DIM);
    // o = causal_attn(qkv)
    attn_kernel<<<dim3(SEQ / BQ, NHEAD, BATCH), 256>>>(qkv, o);
    // x2 = x + o @ w_out^T
    gemm_kernel<2><<<dim3(E_DIM / 128, MTOT / 128), 256>>>(
        o, w_out, nullptr, x, x2, MTOT, E_DIM, E_DIM);
    // h = ln(x2)
    ln_kernel<<<MTOT, 256>>>(x2, h);
    // mb = relu(h @ w_fc^T + b_fc)
    gemm_kernel<1><<<dim3(4 * E_DIM / 128, MTOT / 128), 256>>>(
        h, w_fc, b_fc, nullptr, mb, MTOT, 4 * E_DIM, E_DIM);
    // out = mb @ w_proj^T + b_proj + x2
    gemm_kernel<3><<<dim3(E_DIM / 128, MTOT / 128), 256>>>(
        mb, w_proj, b_proj, x2, out, MTOT, E_DIM, 4 * E_DIM);
}

// round 3
// speedup vs baseline: 2.1293x; 2.1293x over previous
#include <cuda_runtime.h>
#include <cuda_bf16.h>
#include <math_constants.h>
#include <cstdint>

#define E_DIM 1024
#define BATCH 2
#define SEQ   2048
#define NHEAD 16
#define HDIM  64
#define MTOT  4096   // BATCH*SEQ

// ======================= scratch =======================
__device__ __nv_bfloat16 g_h_hi [MTOT * E_DIM];
__device__ __nv_bfloat16 g_h_lo [MTOT * E_DIM];
__device__ float         g_qkv  [MTOT * 3 * E_DIM];
__device__ __nv_bfloat16 g_o_hi [MTOT * E_DIM];
__device__ __nv_bfloat16 g_o_lo [MTOT * E_DIM];
__device__ float         g_x2   [MTOT * E_DIM];
__device__ __nv_bfloat16 g_mb_hi[MTOT * 4 * E_DIM];
__device__ __nv_bfloat16 g_mb_lo[MTOT * 4 * E_DIM];
__device__ __nv_bfloat16 g_wi_hi[3 * E_DIM * E_DIM];
__device__ __nv_bfloat16 g_wi_lo[3 * E_DIM * E_DIM];
__device__ __nv_bfloat16 g_wo_hi[E_DIM * E_DIM];
__device__ __nv_bfloat16 g_wo_lo[E_DIM * E_DIM];
__device__ __nv_bfloat16 g_wf_hi[4 * E_DIM * E_DIM];
__device__ __nv_bfloat16 g_wf_lo[4 * E_DIM * E_DIM];
__device__ __nv_bfloat16 g_wp_hi[E_DIM * 4 * E_DIM];
__device__ __nv_bfloat16 g_wp_lo[E_DIM * 4 * E_DIM];

__device__ __forceinline__ void split_bf16(float x, __nv_bfloat16& h, __nv_bfloat16& l) {
    h = __float2bfloat16_rn(x);
    l = __float2bfloat16_rn(x - __bfloat162float(h));
}

__device__ __forceinline__ uint32_t smem_u32(const void* p) {
    uint32_t a;
    asm("{ .reg .u64 t; cvta.to.shared.u64 t, %1; cvt.u32.u64 %0, t; }" : "=r"(a) : "l"(p));
    return a;
}
__device__ __forceinline__ void ldsm_x4(uint32_t (&r)[4], uint32_t addr) {
    asm volatile("ldmatrix.sync.aligned.m8n8.x4.shared.b16 {%0,%1,%2,%3}, [%4];"
                 : "=r"(r[0]), "=r"(r[1]), "=r"(r[2]), "=r"(r[3]) : "r"(addr));
}
__device__ __forceinline__ void mma16816(float (&d)[4], const uint32_t (&a)[4],
                                         uint32_t b0, uint32_t b1) {
    asm volatile("mma.sync.aligned.m16n8k16.row.col.f32.bf16.bf16.f32 "
                 "{%0,%1,%2,%3}, {%4,%5,%6,%7}, {%8,%9}, {%0,%1,%2,%3};"
                 : "+f"(d[0]), "+f"(d[1]), "+f"(d[2]), "+f"(d[3])
                 : "r"(a[0]), "r"(a[1]), "r"(a[2]), "r"(a[3]), "r"(b0), "r"(b1));
}
__device__ __forceinline__ void cp_async16(uint32_t saddr, const void* gaddr) {
    asm volatile("cp.async.cg.shared.global [%0], [%1], 16;" :: "r"(saddr), "l"(gaddr));
}
__device__ __forceinline__ void cp_commit() {
    asm volatile("cp.async.commit_group;" ::: "memory");
}
template<int N> __device__ __forceinline__ void cp_wait() {
    asm volatile("cp.async.wait_group %0;" :: "n"(N) : "memory");
}

// ======================= weight convert =======================
__global__ __launch_bounds__(256) void cvt_kernel(const float* __restrict__ src,
                                                  __nv_bfloat16* __restrict__ hi,
                                                  __nv_bfloat16* __restrict__ lo,
                                                  int n4) {
    const int stride = gridDim.x * blockDim.x;
    for (int i = blockIdx.x * blockDim.x + threadIdx.x; i < n4; i += stride) {
        float4 v = ((const float4*)src)[i];
        __nv_bfloat16 h0, h1, h2, h3, l0, l1, l2, l3;
        split_bf16(v.x, h0, l0); split_bf16(v.y, h1, l1);
        split_bf16(v.z, h2, l2); split_bf16(v.w, h3, l3);
        __nv_bfloat162* ph = (__nv_bfloat162*)&hi[(size_t)i * 4];
        __nv_bfloat162* pl = (__nv_bfloat162*)&lo[(size_t)i * 4];
        ph[0] = {h0, h1}; ph[1] = {h2, h3};
        pl[0] = {l0, l1}; pl[1] = {l2, l3};
    }
}

// ======================= layernorm (emits hi/lo bf16) =======================
__global__ __launch_bounds__(256) void ln_kernel(const float* __restrict__ x,
                                                 __nv_bfloat16* __restrict__ yhi,
                                                 __nv_bfloat16* __restrict__ ylo) {
    __shared__ float rs[8], rq[8];
    const int row = blockIdx.x;
    const int tid = threadIdx.x;
    float4 v = ((const float4*)(x + (size_t)row * E_DIM))[tid];
    float s  = v.x + v.y + v.z + v.w;
    float sq = v.x*v.x + v.y*v.y + v.z*v.z + v.w*v.w;
#pragma unroll
    for (int o = 16; o; o >>= 1) {
        s  += __shfl_xor_sync(0xffffffffu, s,  o);
        sq += __shfl_xor_sync(0xffffffffu, sq, o);
    }
    if ((tid & 31) == 0) { rs[tid >> 5] = s; rq[tid >> 5] = sq; }
    __syncthreads();
    if (tid < 32) {
        s  = (tid < 8) ? rs[tid] : 0.f;
        sq = (tid < 8) ? rq[tid] : 0.f;
#pragma unroll
        for (int o = 4; o; o >>= 1) {
            s  += __shfl_xor_sync(0xffffffffu, s,  o);
            sq += __shfl_xor_sync(0xffffffffu, sq, o);
        }
        if (tid == 0) { rs[0] = s; rq[0] = sq; }
    }
    __syncthreads();
    const float mean = rs[0] * (1.0f / E_DIM);
    const float var  = rq[0] * (1.0f / E_DIM) - mean * mean;
    const float rstd = rsqrtf(var + 1e-5f);
    float y0 = (v.x - mean) * rstd, y1 = (v.y - mean) * rstd;
    float y2 = (v.z - mean) * rstd, y3 = (v.w - mean) * rstd;
    __nv_bfloat16 h0, h1, h2, h3, l0, l1, l2, l3;
    split_bf16(y0, h0, l0); split_bf16(y1, h1, l1);
    split_bf16(y2, h2, l2); split_bf16(y3, h3, l3);
    __nv_bfloat162* ph = (__nv_bfloat162*)&yhi[(size_t)row * E_DIM + tid * 4];
    __nv_bfloat162* pl = (__nv_bfloat162*)&ylo[(size_t)row * E_DIM + tid * 4];
    ph[0] = {h0, h1}; ph[1] = {h2, h3};
    pl[0] = {l0, l1}; pl[1] = {l2, l3};
}

// ======================= tensor-core GEMM (mma.sync bf16, hi/lo x3) =======================
// C[M,N] = A[M,K] * B[N,K]^T
// MODE 0: fp32 out | 1: relu(+bias) -> bf16 hi/lo | 2: +res fp32 | 3: +bias+res fp32
#define TILE_BYTES  16384               // 128 rows x 128 bytes (64 bf16)
#define STAGE_BYTES (4 * TILE_BYTES)    // Ah, Al, Bh, Bl
#define GEMM_SMEM   (2 * STAGE_BYTES)   // double buffer = 128 KB

template<int MODE>
__global__ __launch_bounds__(256) void gemm_tc(
    const __nv_bfloat16* __restrict__ Ah, const __nv_bfloat16* __restrict__ Al,
    const __nv_bfloat16* __restrict__ Bh, const __nv_bfloat16* __restrict__ Bl,
    const float* __restrict__ bias, const float* __restrict__ res,
    float* __restrict__ Cf, __nv_bfloat16* __restrict__ Chi,
    __nv_bfloat16* __restrict__ Clo, int M, int N, int K)
{
    extern __shared__ char smem[];
    const uint32_t sbase = smem_u32(smem);
    const int tid  = threadIdx.x;
    const int wid  = tid >> 5;
    const int lane = tid & 31;
    const int row0 = blockIdx.y * 128;
    const int col0 = blockIdx.x * 128;
    const int wm = (wid & 1) * 64;     // warp M offset
    const int wn = (wid >> 1) * 32;    // warp N offset

    float acc[4][4][4];
#pragma unroll
    for (int i = 0; i < 4; i++)
#pragma unroll
        for (int j = 0; j < 4; j++)
#pragma unroll
            for (int k = 0; k < 4; k++) acc[i][j][k] = 0.f;

    const int NC = K >> 6;

    auto issue_stage = [&](int c) {
        const uint32_t st = sbase + (c & 1) * STAGE_BYTES;
        const int k0 = c << 6;
#pragma unroll
        for (int t = 0; t < 4; t++) {
            const __nv_bfloat16* g = (t == 0) ? Ah : (t == 1) ? Al : (t == 2) ? Bh : Bl;
            const int rbase = (t < 2) ? row0 : col0;
            const uint32_t tb = st + t * TILE_BYTES;
#pragma unroll
            for (int i = 0; i < 4; i++) {
                const int idx = tid + i * 256;
                const int r = idx >> 3, cc = idx & 7;
                cp_async16(tb + r * 128 + ((cc ^ (r & 7)) << 4),
                           g + (size_t)(rbase + r) * K + k0 + cc * 8);
            }
        }
        cp_commit();
    };

    issue_stage(0);

    for (int c = 0; c < NC; c++) {
        if (c + 1 < NC) { issue_stage(c + 1); cp_wait<1>(); }
        else            { cp_wait<0>(); }
        __syncthreads();

        const uint32_t st  = sbase + (c & 1) * STAGE_BYTES;
        const uint32_t sAh = st;
        const uint32_t sAl = st + TILE_BYTES;
        const uint32_t sBh = st + 2 * TILE_BYTES;
        const uint32_t sBl = st + 3 * TILE_BYTES;
        const int g  = lane >> 3;
        const int lr = lane & 7;

#pragma unroll
        for (int ks = 0; ks < 4; ks++) {
            const int kc0 = ks * 2;
            uint32_t ah[4][4], al[4][4], bh[4][2], bl[4][2];
#pragma unroll
            for (int mt = 0; mt < 4; mt++) {
                const int row = wm + mt * 16 + lr + (g & 1) * 8;
                const int ch  = kc0 + (g >> 1);
                const uint32_t off = row * 128 + ((ch ^ (row & 7)) << 4);
                ldsm_x4(ah[mt], sAh + off);
                ldsm_x4(al[mt], sAl + off);
            }
#pragma unroll
            for (int np = 0; np < 2; np++) {
                const int row = wn + np * 16 + lr + (g >> 1) * 8;
                const int ch  = kc0 + (g & 1);
                const uint32_t off = row * 128 + ((ch ^ (row & 7)) << 4);
                uint32_t t0[4], t1[4];
                ldsm_x4(t0, sBh + off);
                ldsm_x4(t1, sBl + off);
                bh[np*2][0] = t0[0]; bh[np*2][1] = t0[1];
                bh[np*2+1][0] = t0[2]; bh[np*2+1][1] = t0[3];
                bl[np*2][0] = t1[0]; bl[np*2][1] = t1[1];
                bl[np*2+1][0] = t1[2]; bl[np*2+1][1] = t1[3];
            }
#pragma unroll
            for (int mt = 0; mt < 4; mt++)
#pragma unroll
                for (int nt = 0; nt < 4; nt++) {
                    mma16816(acc[mt][nt], ah[mt], bh[nt][0], bh[nt][1]);
                    mma16816(acc[mt][nt], ah[mt], bl[nt][0], bl[nt][1]);
                    mma16816(acc[mt][nt], al[mt], bh[nt][0], bh[nt][1]);
                }
        }
        __syncthreads();
    }

#pragma unroll
    for (int mt = 0; mt < 4; mt++) {
#pragma unroll
        for (int nt = 0; nt < 4; nt++) {
            const int r0 = row0 + wm + mt * 16 + (lane >> 2);
            const int r1 = r0 + 8;
            const int cc = col0 + wn + nt * 8 + (lane & 3) * 2;
            float v0 = acc[mt][nt][0], v1 = acc[mt][nt][1];
            float v2 = acc[mt][nt][2], v3 = acc[mt][nt][3];
            if (MODE == 1 || MODE == 3) {
                const float b0 = bias[cc], b1 = bias[cc + 1];
                v0 += b0; v1 += b1; v2 += b0; v3 += b1;
            }
            if (MODE == 1) {
                v0 = fmaxf(v0, 0.f); v1 = fmaxf(v1, 0.f);
                v2 = fmaxf(v2, 0.f); v3 = fmaxf(v3, 0.f);
            }
            if (MODE == 2 || MODE == 3) {
                float2 ra = *(const float2*)&res[(size_t)r0 * N + cc];
                float2 rb = *(const float2*)&res[(size_t)r1 * N + cc];
                v0 += ra.x; v1 += ra.y; v2 += rb.x; v3 += rb.y;
            }
            if (MODE == 1) {
                __nv_bfloat16 h0, h1, h2, h3, l0, l1, l2, l3;
                split_bf16(v0, h0, l0); split_bf16(v1, h1, l1);
                split_bf16(v2, h2, l2); split_bf16(v3, h3, l3);
                *(__nv_bfloat162*)&Chi[(size_t)r0 * N + cc] = {h0, h1};
                *(__nv_bfloat162*)&Chi[(size_t)r1 * N + cc] = {h2, h3};
                *(__nv_bfloat162*)&Clo[(size_t)r0 * N + cc] = {l0, l1};
                *(__nv_bfloat162*)&Clo[(size_t)r1 * N + cc] = {l2, l3};
            } else {
                *(float2*)&Cf[(size_t)r0 * N + cc] = {v0, v1};
                *(float2*)&Cf[(size_t)r1 * N + cc] = {v2, v3};
            }
        }
    }
}

// ======================= causal flash attention (fp32 SIMT) =======================
#define BQ  64
#define BKV 32
__global__ __launch_bounds__(256) void attn_kernel(const float* __restrict__ qkv,
                                                   __nv_bfloat16* __restrict__ ohi,
                                                   __nv_bfloat16* __restrict__ olo)
{
    __shared__ float Qs[BQ][HDIM + 1];
    __shared__ float Ks[BKV][HDIM + 1];
    __shared__ float Vs[BKV][HDIM + 1];
    __shared__ float Ss[BQ][BKV + 1];
    __shared__ float m_sh[BQ], l_sh[BQ], c_sh[BQ];

    const int tid = threadIdx.x;
    const int q0  = blockIdx.x * BQ;
    const int h   = blockIdx.y;
    const int b   = blockIdx.z;
    const size_t base = (size_t)b * SEQ * 3 * E_DIM + (size_t)h * HDIM;

#pragma unroll
    for (int i = 0; i < 4; i++) {
        const int f = tid + i * 256;
        const int r = f >> 4;
        const int c = (f & 15) * 4;
        float4 v = *(const float4*)&qkv[base + (size_t)(q0 + r) * 3 * E_DIM + c];
        Qs[r][c] = v.x; Qs[r][c+1] = v.y; Qs[r][c+2] = v.z; Qs[r][c+3] = v.w;
    }
    if (tid < BQ) { m_sh[tid] = -CUDART_INF_F; l_sh[tid] = 0.f; }

    const int tx = tid & 15, ty = tid >> 4;
    float oacc[4][4];
#pragma unroll
    for (int i = 0; i < 4; i++)
#pragma unroll
        for (int j = 0; j < 4; j++) oacc[i][j] = 0.f;

    const float scale = 0.125f;

    for (int k0 = 0; k0 <= q0 + BQ - 1; k0 += BKV) {
        __syncthreads();
#pragma unroll
        for (int i = 0; i < 2; i++) {
            const int f = tid + i * 256;
            const int r = f >> 4;
            const int c = (f & 15) * 4;
            float4 kv = *(const float4*)&qkv[base + E_DIM     + (size_t)(k0 + r) * 3 * E_DIM + c];
            Ks[r][c] = kv.x; Ks[r][c+1] = kv.y; Ks[r][c+2] = kv.z; Ks[r][c+3] = kv.w;
            float4 vv = *(const float4*)&qkv[base + 2 * E_DIM + (size_t)(k0 + r) * 3 * E_DIM + c];
            Vs[r][c] = vv.x; Vs[r][c+1] = vv.y; Vs[r][c+2] = vv.z; Vs[r][c+3] = vv.w;
        }
        __syncthreads();

        float s[4][2] = {{0.f,0.f},{0.f,0.f},{0.f,0.f},{0.f,0.f}};
#pragma unroll 8
        for (int d = 0; d < HDIM; d++) {
            const float k0v = Ks[tx * 2 + 0][d];
            const float k1v = Ks[tx * 2 + 1][d];
#pragma unroll
            for (int i = 0; i < 4; i++) {
                const float q = Qs[ty * 4 + i][d];
                s[i][0] = fmaf(q, k0v, s[i][0]);
                s[i][1] = fmaf(q, k1v, s[i][1]);
            }
        }
#pragma unroll
        for (int i = 0; i < 4; i++)
#pragma unroll
            for (int j = 0; j < 2; j++) {
                const int qi = q0 + ty * 4 + i;
                const int ki = k0 + tx * 2 + j;
                Ss[ty * 4 + i][tx * 2 + j] = (ki <= qi) ? s[i][j] * scale : -CUDART_INF_F;
            }
        __syncthreads();

        if (tid < BQ) {
            const int rr = tid;
            float mx = -CUDART_INF_F;
#pragma unroll
            for (int c = 0; c < BKV; c++) mx = fmaxf(mx, Ss[rr][c]);
            const float mo = m_sh[rr];
            const float nm = fmaxf(mo, mx);
            const float corr = __expf(mo - nm);
            float sum = 0.f;
#pragma unroll
            for (int c = 0; c < BKV; c++) {
                const float p = __expf(Ss[rr][c] - nm);
                Ss[rr][c] = p;
                sum += p;
            }
            l_sh[rr] = l_sh[rr] * corr + sum;
            m_sh[rr] = nm;
            c_sh[rr] = corr;
        }
        __syncthreads();

#pragma unroll
        for (int i = 0; i < 4; i++) {
            const float corr = c_sh[ty * 4 + i];
#pragma unroll
            for (int j = 0; j < 4; j++) oacc[i][j] *= corr;
        }
#pragma unroll 4
        for (int kk = 0; kk < BKV; kk++) {
            float vv[4];
#pragma unroll
            for (int j = 0; j < 4; j++) vv[j] = Vs[kk][tx * 4 + j];
#pragma unroll
            for (int i = 0; i < 4; i++) {
                const float p = Ss[ty * 4 + i][kk];
#pragma unroll
                for (int j = 0; j < 4; j++) oacc[i][j] = fmaf(p, vv[j], oacc[i][j]);
            }
        }
    }

#pragma unroll
    for (int i = 0; i < 4; i++) {
        const int r = ty * 4 + i;
        const float inv = 1.0f / l_sh[r];
        float y0 = oacc[i][0] * inv, y1 = oacc[i][1] * inv;
        float y2 = oacc[i][2] * inv, y3 = oacc[i][3] * inv;
        __nv_bfloat16 h0, h1, h2, h3, l0, l1, l2, l3;
        split_bf16(y0, h0, l0); split_bf16(y1, h1, l1);
        split_bf16(y2, h2, l2); split_bf16(y3, h3, l3);
        const size_t idx = ((size_t)b * SEQ + q0 + r) * E_DIM + h * HDIM + tx * 4;
        __nv_bfloat162* ph = (__nv_bfloat162*)&ohi[idx];
        __nv_bfloat162* pl = (__nv_bfloat162*)&olo[idx];
        ph[0] = {h0, h1}; ph[1] = {h2, h3};
        pl[0] = {l0, l1}; pl[1] = {l2, l3};
    }
}

// ======================= launch =======================
extern "C" void kernel_launch(void* const* d_in, const int* in_sizes, int n_in,
                              void* d_out, int out_size) {
    const float* x      = (const float*)d_in[0];
    const float* w_in   = (const float*)d_in[1];
    const float* w_out  = (const float*)d_in[2];
    const float* w_fc   = (const float*)d_in[3];
    const float* b_fc   = (const float*)d_in[4];
    const float* w_proj = (const float*)d_in[5];
    const float* b_proj = (const float*)d_in[6];
    float* out = (float*)d_out;

    __nv_bfloat16 *h_hi, *h_lo, *o_hi, *o_lo, *mb_hi, *mb_lo;
    __nv_bfloat16 *wi_hi, *wi_lo, *wo_hi, *wo_lo, *wf_hi, *wf_lo, *wp_hi, *wp_lo;
    float *qkv, *x2;
    cudaGetSymbolAddress((void**)&h_hi,  g_h_hi);  cudaGetSymbolAddress((void**)&h_lo,  g_h_lo);
    cudaGetSymbolAddress((void**)&qkv,   g_qkv);
    cudaGetSymbolAddress((void**)&o_hi,  g_o_hi);  cudaGetSymbolAddress((void**)&o_lo,  g_o_lo);
    cudaGetSymbolAddress((void**)&x2,    g_x2);
    cudaGetSymbolAddress((void**)&mb_hi, g_mb_hi); cudaGetSymbolAddress((void**)&mb_lo, g_mb_lo);
    cudaGetSymbolAddress((void**)&wi_hi, g_wi_hi); cudaGetSymbolAddress((void**)&wi_lo, g_wi_lo);
    cudaGetSymbolAddress((void**)&wo_hi, g_wo_hi); cudaGetSymbolAddress((void**)&wo_lo, g_wo_lo);
    cudaGetSymbolAddress((void**)&wf_hi, g_wf_hi); cudaGetSymbolAddress((void**)&wf_lo, g_wf_lo);
    cudaGetSymbolAddress((void**)&wp_hi, g_wp_hi); cudaGetSymbolAddress((void**)&wp_lo, g_wp_lo);

    cudaFuncSetAttribute(gemm_tc<0>, cudaFuncAttributeMaxDynamicSharedMemorySize, GEMM_SMEM);
    cudaFuncSetAttribute(gemm_tc<1>, cudaFuncAttributeMaxDynamicSharedMemorySize, GEMM_SMEM);
    cudaFuncSetAttribute(gemm_tc<2>, cudaFuncAttributeMaxDynamicSharedMemorySize, GEMM_SMEM);
    cudaFuncSetAttribute(gemm_tc<3>, cudaFuncAttributeMaxDynamicSharedMemorySize, GEMM_SMEM);

    // weight splits
    cvt_kernel<<<512, 256>>>(w_in,   wi_hi, wi_lo, 3 * E_DIM * E_DIM / 4);
    cvt_kernel<<<512, 256>>>(w_out,  wo_hi, wo_lo, E_DIM * E_DIM / 4);
    cvt_kernel<<<512, 256>>>(w_fc,   wf_hi, wf_lo, 4 * E_DIM * E_DIM / 4);
    cvt_kernel<<<512, 256>>>(w_proj, wp_hi, wp_lo, E_DIM * 4 * E_DIM / 4);

    // h = ln(x) -> bf16 split
    ln_kernel<<<MTOT, 256>>>(x, h_hi, h_lo);
    // qkv = h @ w_in^T
    gemm_tc<0><<<dim3(3 * E_DIM / 128, MTOT / 128), 256, GEMM_SMEM>>>(
        h_hi, h_lo, wi_hi, wi_lo, nullptr, nullptr, qkv, nullptr, nullptr,
        MTOT, 3 * E_DIM, E_DIM);
    // o = causal_attn(qkv) -> bf16 split
    attn_kernel<<<dim3(SEQ / BQ, NHEAD, BATCH), 256>>>(qkv, o_hi, o_lo);
    // x2 = x + o @ w_out^T
    gemm_tc<2><<<dim3(E_DIM / 128, MTOT / 128), 256, GEMM_SMEM>>>(
        o_hi, o_lo, wo_hi, wo_lo, nullptr, x, x2, nullptr, nullptr,
        MTOT, E_DIM, E_DIM);
    // h = ln(x2) -> bf16 split
    ln_kernel<<<MTOT, 256>>>(x2, h_hi, h_lo);
    // mb = relu(h @ w_fc^T + b_fc) -> bf16 split
    gemm_tc<1><<<dim3(4 * E_DIM / 128, MTOT / 128), 256, GEMM_SMEM>>>(
        h_hi, h_lo, wf_hi, wf_lo, b_fc, nullptr, nullptr, mb_hi, mb_lo,
        MTOT, 4 * E_DIM, E_DIM);
    // out = mb @ w_proj^T + b_proj + x2
    gemm_tc<3><<<dim3(E_DIM / 128, MTOT / 128), 256, GEMM_SMEM>>>(
        mb_hi, mb_lo, wp_hi, wp_lo, b_proj, x2, out, nullptr, nullptr,
        MTOT, E_DIM, 4 * E_DIM);
}

// round 4
// speedup vs baseline: 3.3555x; 1.5759x over previous
#include <cuda_runtime.h>
#include <cuda_bf16.h>
#include <math_constants.h>
#include <cstdint>

#define E_DIM 1024
#define BATCH 2
#define SEQ   2048
#define NHEAD 16
#define HDIM  64
#define MTOT  4096   // BATCH*SEQ

// ======================= scratch =======================
__device__ __nv_bfloat16 g_h_hi [MTOT * E_DIM];
__device__ __nv_bfloat16 g_h_lo [MTOT * E_DIM];
__device__ __nv_bfloat16 g_o_hi [MTOT * E_DIM];
__device__ __nv_bfloat16 g_o_lo [MTOT * E_DIM];
__device__ float         g_x2   [MTOT * E_DIM];
__device__ __nv_bfloat16 g_mb_hi[MTOT * 4 * E_DIM];   // reused: qkv hi, then mlp hidden hi
__device__ __nv_bfloat16 g_mb_lo[MTOT * 4 * E_DIM];   // reused: qkv lo, then mlp hidden lo
__device__ __nv_bfloat16 g_wi_hi[3 * E_DIM * E_DIM];
__device__ __nv_bfloat16 g_wi_lo[3 * E_DIM * E_DIM];
__device__ __nv_bfloat16 g_wo_hi[E_DIM * E_DIM];
__device__ __nv_bfloat16 g_wo_lo[E_DIM * E_DIM];
__device__ __nv_bfloat16 g_wf_hi[4 * E_DIM * E_DIM];
__device__ __nv_bfloat16 g_wf_lo[4 * E_DIM * E_DIM];
__device__ __nv_bfloat16 g_wp_hi[E_DIM * 4 * E_DIM];
__device__ __nv_bfloat16 g_wp_lo[E_DIM * 4 * E_DIM];

__device__ __forceinline__ void split_bf16(float x, __nv_bfloat16& h, __nv_bfloat16& l) {
    h = __float2bfloat16_rn(x);
    l = __float2bfloat16_rn(x - __bfloat162float(h));
}
__device__ __forceinline__ void split_pack(float f0, float f1, uint32_t& h, uint32_t& l) {
    __nv_bfloat16 h0, l0, h1, l1;
    split_bf16(f0, h0, l0); split_bf16(f1, h1, l1);
    __nv_bfloat162 hh = {h0, h1}, ll = {l0, l1};
    h = *(uint32_t*)&hh; l = *(uint32_t*)&ll;
}

__device__ __forceinline__ uint32_t smem_u32(const void* p) {
    uint32_t a;
    asm("{ .reg .u64 t; cvta.to.shared.u64 t, %1; cvt.u32.u64 %0, t; }" : "=r"(a) : "l"(p));
    return a;
}
__device__ __forceinline__ void ldsm_x4(uint32_t (&r)[4], uint32_t addr) {
    asm volatile("ldmatrix.sync.aligned.m8n8.x4.shared.b16 {%0,%1,%2,%3}, [%4];"
                 : "=r"(r[0]), "=r"(r[1]), "=r"(r[2]), "=r"(r[3]) : "r"(addr));
}
__device__ __forceinline__ void ldsm_x2_trans(uint32_t (&r)[2], uint32_t addr) {
    asm volatile("ldmatrix.sync.aligned.m8n8.x2.trans.shared.b16 {%0,%1}, [%2];"
                 : "=r"(r[0]), "=r"(r[1]) : "r"(addr));
}
__device__ __forceinline__ void mma16816(float (&d)[4], const uint32_t (&a)[4],
                                         uint32_t b0, uint32_t b1) {
    asm volatile("mma.sync.aligned.m16n8k16.row.col.f32.bf16.bf16.f32 "
                 "{%0,%1,%2,%3}, {%4,%5,%6,%7}, {%8,%9}, {%0,%1,%2,%3};"
                 : "+f"(d[0]), "+f"(d[1]), "+f"(d[2]), "+f"(d[3])
                 : "r"(a[0]), "r"(a[1]), "r"(a[2]), "r"(a[3]), "r"(b0), "r"(b1));
}
__device__ __forceinline__ void cp_async16(uint32_t saddr, const void* gaddr) {
    asm volatile("cp.async.cg.shared.global [%0], [%1], 16;" :: "r"(saddr), "l"(gaddr));
}
__device__ __forceinline__ void cp_commit() {
    asm volatile("cp.async.commit_group;" ::: "memory");
}
template<int N> __device__ __forceinline__ void cp_wait() {
    asm volatile("cp.async.wait_group %0;" :: "n"(N) : "memory");
}

// ======================= weight convert =======================
__global__ __launch_bounds__(256) void cvt_kernel(const float* __restrict__ src,
                                                  __nv_bfloat16* __restrict__ hi,
                                                  __nv_bfloat16* __restrict__ lo,
                                                  int n4) {
    const int stride = gridDim.x * blockDim.x;
    for (int i = blockIdx.x * blockDim.x + threadIdx.x; i < n4; i += stride) {
        float4 v = ((const float4*)src)[i];
        __nv_bfloat16 h0, h1, h2, h3, l0, l1, l2, l3;
        split_bf16(v.x, h0, l0); split_bf16(v.y, h1, l1);
        split_bf16(v.z, h2, l2); split_bf16(v.w, h3, l3);
        __nv_bfloat162* ph = (__nv_bfloat162*)&hi[(size_t)i * 4];
        __nv_bfloat162* pl = (__nv_bfloat162*)&lo[(size_t)i * 4];
        ph[0] = {h0, h1}; ph[1] = {h2, h3};
        pl[0] = {l0, l1}; pl[1] = {l2, l3};
    }
}

// ======================= layernorm (emits hi/lo bf16) =======================
__global__ __launch_bounds__(256) void ln_kernel(const float* __restrict__ x,
                                                 __nv_bfloat16* __restrict__ yhi,
                                                 __nv_bfloat16* __restrict__ ylo) {
    __shared__ float rs[8], rq[8];
    const int row = blockIdx.x;
    const int tid = threadIdx.x;
    float4 v = ((const float4*)(x + (size_t)row * E_DIM))[tid];
    float s  = v.x + v.y + v.z + v.w;
    float sq = v.x*v.x + v.y*v.y + v.z*v.z + v.w*v.w;
#pragma unroll
    for (int o = 16; o; o >>= 1) {
        s  += __shfl_xor_sync(0xffffffffu, s,  o);
        sq += __shfl_xor_sync(0xffffffffu, sq, o);
    }
    if ((tid & 31) == 0) { rs[tid >> 5] = s; rq[tid >> 5] = sq; }
    __syncthreads();
    if (tid < 32) {
        s  = (tid < 8) ? rs[tid] : 0.f;
        sq = (tid < 8) ? rq[tid] : 0.f;
#pragma unroll
        for (int o = 4; o; o >>= 1) {
            s  += __shfl_xor_sync(0xffffffffu, s,  o);
            sq += __shfl_xor_sync(0xffffffffu, sq, o);
        }
        if (tid == 0) { rs[0] = s; rq[0] = sq; }
    }
    __syncthreads();
    const float mean = rs[0] * (1.0f / E_DIM);
    const float var  = rq[0] * (1.0f / E_DIM) - mean * mean;
    const float rstd = rsqrtf(var + 1e-5f);
    float y0 = (v.x - mean) * rstd, y1 = (v.y - mean) * rstd;
    float y2 = (v.z - mean) * rstd, y3 = (v.w - mean) * rstd;
    __nv_bfloat16 h0, h1, h2, h3, l0, l1, l2, l3;
    split_bf16(y0, h0, l0); split_bf16(y1, h1, l1);
    split_bf16(y2, h2, l2); split_bf16(y3, h3, l3);
    __nv_bfloat162* ph = (__nv_bfloat162*)&yhi[(size_t)row * E_DIM + tid * 4];
    __nv_bfloat162* pl = (__nv_bfloat162*)&ylo[(size_t)row * E_DIM + tid * 4];
    ph[0] = {h0, h1}; ph[1] = {h2, h3};
    pl[0] = {l0, l1}; pl[1] = {l2, l3};
}

// ======================= tensor-core GEMM (mma.sync bf16, hi/lo x3) =======================
// C[M,N] = A[M,K] * B[N,K]^T
// MODE 0: fp32 out | 1: relu(+bias)->bf16 hi/lo | 2: +res fp32 | 3: +bias+res fp32 | 4: bf16 hi/lo
#define TILE_BYTES  16384               // 128 rows x 128 bytes (64 bf16)
#define STAGE_BYTES (4 * TILE_BYTES)    // Ah, Al, Bh, Bl
#define GEMM_SMEM   (2 * STAGE_BYTES)   // double buffer = 128 KB

template<int MODE>
__global__ __launch_bounds__(256) void gemm_tc(
    const __nv_bfloat16* __restrict__ Ah, const __nv_bfloat16* __restrict__ Al,
    const __nv_bfloat16* __restrict__ Bh, const __nv_bfloat16* __restrict__ Bl,
    const float* __restrict__ bias, const float* __restrict__ res,
    float* __restrict__ Cf, __nv_bfloat16* __restrict__ Chi,
    __nv_bfloat16* __restrict__ Clo, int M, int N, int K)
{
    extern __shared__ char smem[];
    const uint32_t sbase = smem_u32(smem);
    const int tid  = threadIdx.x;
    const int wid  = tid >> 5;
    const int lane = tid & 31;
    const int row0 = blockIdx.y * 128;
    const int col0 = blockIdx.x * 128;
    const int wm = (wid & 1) * 64;
    const int wn = (wid >> 1) * 32;

    float acc[4][4][4];
#pragma unroll
    for (int i = 0; i < 4; i++)
#pragma unroll
        for (int j = 0; j < 4; j++)
#pragma unroll
            for (int k = 0; k < 4; k++) acc[i][j][k] = 0.f;

    const int NC = K >> 6;

    auto issue_stage = [&](int c) {
        const uint32_t st = sbase + (c & 1) * STAGE_BYTES;
        const int k0 = c << 6;
#pragma unroll
        for (int t = 0; t < 4; t++) {
            const __nv_bfloat16* g = (t == 0) ? Ah : (t == 1) ? Al : (t == 2) ? Bh : Bl;
            const int rbase = (t < 2) ? row0 : col0;
            const uint32_t tb = st + t * TILE_BYTES;
#pragma unroll
            for (int i = 0; i < 4; i++) {
                const int idx = tid + i * 256;
                const int r = idx >> 3, cc = idx & 7;
                cp_async16(tb + r * 128 + ((cc ^ (r & 7)) << 4),
                           g + (size_t)(rbase + r) * K + k0 + cc * 8);
            }
        }
        cp_commit();
    };

    issue_stage(0);

    for (int c = 0; c < NC; c++) {
        if (c + 1 < NC) { issue_stage(c + 1); cp_wait<1>(); }
        else            { cp_wait<0>(); }
        __syncthreads();

        const uint32_t st  = sbase + (c & 1) * STAGE_BYTES;
        const uint32_t sAh = st;
        const uint32_t sAl = st + TILE_BYTES;
        const uint32_t sBh = st + 2 * TILE_BYTES;
        const uint32_t sBl = st + 3 * TILE_BYTES;
        const int g  = lane >> 3;
        const int lr = lane & 7;

#pragma unroll
        for (int ks = 0; ks < 4; ks++) {
            const int kc0 = ks * 2;
            uint32_t ah[4][4], al[4][4], bh[4][2], bl[4][2];
#pragma unroll
            for (int mt = 0; mt < 4; mt++) {
                const int row = wm + mt * 16 + lr + (g & 1) * 8;
                const int ch  = kc0 + (g >> 1);
                const uint32_t off = row * 128 + ((ch ^ (row & 7)) << 4);
                ldsm_x4(ah[mt], sAh + off);
                ldsm_x4(al[mt], sAl + off);
            }
#pragma unroll
            for (int np = 0; np < 2; np++) {
                const int row = wn + np * 16 + lr + (g >> 1) * 8;
                const int ch  = kc0 + (g & 1);
                const uint32_t off = row * 128 + ((ch ^ (row & 7)) << 4);
                uint32_t t0[4], t1[4];
                ldsm_x4(t0, sBh + off);
                ldsm_x4(t1, sBl + off);
                bh[np*2][0] = t0[0]; bh[np*2][1] = t0[1];
                bh[np*2+1][0] = t0[2]; bh[np*2+1][1] = t0[3];
                bl[np*2][0] = t1[0]; bl[np*2][1] = t1[1];
                bl[np*2+1][0] = t1[2]; bl[np*2+1][1] = t1[3];
            }
#pragma unroll
            for (int mt = 0; mt < 4; mt++)
#pragma unroll
                for (int nt = 0; nt < 4; nt++) {
                    mma16816(acc[mt][nt], ah[mt], bh[nt][0], bh[nt][1]);
                    mma16816(acc[mt][nt], ah[mt], bl[nt][0], bl[nt][1]);
                    mma16816(acc[mt][nt], al[mt], bh[nt][0], bh[nt][1]);
                }
        }
        __syncthreads();
    }

#pragma unroll
    for (int mt = 0; mt < 4; mt++) {
#pragma unroll
        for (int nt = 0; nt < 4; nt++) {
            const int r0 = row0 + wm + mt * 16 + (lane >> 2);
            const int r1 = r0 + 8;
            const int cc = col0 + wn + nt * 8 + (lane & 3) * 2;
            float v0 = acc[mt][nt][0], v1 = acc[mt][nt][1];
            float v2 = acc[mt][nt][2], v3 = acc[mt][nt][3];
            if (MODE == 1 || MODE == 3) {
                const float b0 = bias[cc], b1 = bias[cc + 1];
                v0 += b0; v1 += b1; v2 += b0; v3 += b1;
            }
            if (MODE == 1) {
                v0 = fmaxf(v0, 0.f); v1 = fmaxf(v1, 0.f);
                v2 = fmaxf(v2, 0.f); v3 = fmaxf(v3, 0.f);
            }
            if (MODE == 2 || MODE == 3) {
                float2 ra = *(const float2*)&res[(size_t)r0 * N + cc];
                float2 rb = *(const float2*)&res[(size_t)r1 * N + cc];
                v0 += ra.x; v1 += ra.y; v2 += rb.x; v3 += rb.y;
            }
            if (MODE == 1 || MODE == 4) {
                __nv_bfloat16 h0, h1, h2, h3, l0, l1, l2, l3;
                split_bf16(v0, h0, l0); split_bf16(v1, h1, l1);
                split_bf16(v2, h2, l2); split_bf16(v3, h3, l3);
                *(__nv_bfloat162*)&Chi[(size_t)r0 * N + cc] = {h0, h1};
                *(__nv_bfloat162*)&Chi[(size_t)r1 * N + cc] = {h2, h3};
                *(__nv_bfloat162*)&Clo[(size_t)r0 * N + cc] = {l0, l1};
                *(__nv_bfloat162*)&Clo[(size_t)r1 * N + cc] = {l2, l3};
            } else {
                *(float2*)&Cf[(size_t)r0 * N + cc] = {v0, v1};
                *(float2*)&Cf[(size_t)r1 * N + cc] = {v2, v3};
            }
        }
    }
}

// ======================= MMA causal flash attention =======================
// CTA: 128 q rows (8 warps x 16), KV tiles of 64, double-buffered.
// smem: Qh 16K | Ql 16K | stage0 {Kh,Kl,Vh,Vl 8K each} | stage1 {...} = 96 KB
#define ATT_SMEM 98304

__global__ __launch_bounds__(256) void attn_mma(
    const __nv_bfloat16* __restrict__ qkvh, const __nv_bfloat16* __restrict__ qkvl,
    __nv_bfloat16* __restrict__ ohi, __nv_bfloat16* __restrict__ olo)
{
    extern __shared__ char smem[];
    const uint32_t sb = smem_u32(smem);
    const int tid = threadIdx.x, wid = tid >> 5, lane = tid & 31;
    const int qb = (int)gridDim.x - 1 - (int)blockIdx.x;   // longest blocks first
    const int q0 = qb * 128;
    const int h  = blockIdx.y, b = blockIdx.z;
    const int LD = 3 * E_DIM;
    const size_t base = (size_t)b * SEQ * LD + (size_t)h * HDIM;

    const uint32_t sQh = sb, sQl = sb + 16384;

    // Q loads (same async group as KV stage 0)
#pragma unroll
    for (int i = 0; i < 4; i++) {
        const int idx = tid + i * 256;
        const int r = idx >> 3, cc = idx & 7;
        const uint32_t soff = r * 128 + ((cc ^ (r & 7)) << 4);
        cp_async16(sQh + soff, qkvh + base + (size_t)(q0 + r) * LD + cc * 8);
        cp_async16(sQl + soff, qkvl + base + (size_t)(q0 + r) * LD + cc * 8);
    }
    auto issue_kv = [&](int t) {
        const uint32_t st = sb + 32768 + (t & 1) * 32768;
        const int k0 = t * 64;
#pragma unroll
        for (int i = 0; i < 2; i++) {
            const int idx = tid + i * 256;
            const int r = idx >> 3, cc = idx & 7;
            const uint32_t soff = r * 128 + ((cc ^ (r & 7)) << 4);
            const size_t gk = base + E_DIM     + (size_t)(k0 + r) * LD + cc * 8;
            const size_t gv = base + 2 * E_DIM + (size_t)(k0 + r) * LD + cc * 8;
            cp_async16(st +         soff, qkvh + gk);
            cp_async16(st + 8192  + soff, qkvl + gk);
            cp_async16(st + 16384 + soff, qkvh + gv);
            cp_async16(st + 24576 + soff, qkvl + gv);
        }
        cp_commit();
    };
    issue_kv(0);

    const int ntiles = (q0 >> 6) + 2;
    const int g = lane >> 2, tig = lane & 3;
    const int lr = lane & 7, gg = lane >> 3;

    float oacc[8][4];
#pragma unroll
    for (int j = 0; j < 8; j++)
#pragma unroll
        for (int e = 0; e < 4; e++) oacc[j][e] = 0.f;
    float m0 = -CUDART_INF_F, m1 = -CUDART_INF_F, l0 = 0.f, l1 = 0.f;
    uint32_t qfh[4][4], qfl[4][4];
    const float scale = 0.125f;

    for (int t = 0; t < ntiles; t++) {
        if (t + 1 < ntiles) { issue_kv(t + 1); cp_wait<1>(); }
        else                { cp_wait<0>(); }
        __syncthreads();
        if (t == 0) {
            const int row = wid * 16 + lr + (gg & 1) * 8;
#pragma unroll
            for (int kc = 0; kc < 4; kc++) {
                const int ch = kc * 2 + (gg >> 1);
                const uint32_t off = row * 128 + ((ch ^ (row & 7)) << 4);
                ldsm_x4(qfh[kc], sQh + off);
                ldsm_x4(qfl[kc], sQl + off);
            }
        }
        const uint32_t sKh = sb + 32768 + (t & 1) * 32768;
        const uint32_t sKl = sKh + 8192;
        const uint32_t sVh = sKh + 16384;
        const uint32_t sVl = sKh + 24576;

        // ---- S = Q K^T (3-pass hi/lo) ----
        float S[8][4];
#pragma unroll
        for (int j = 0; j < 8; j++)
#pragma unroll
            for (int e = 0; e < 4; e++) S[j][e] = 0.f;
#pragma unroll
        for (int kc = 0; kc < 4; kc++) {
            uint32_t bh[8][2], bl[8][2];
#pragma unroll
            for (int jp = 0; jp < 4; jp++) {
                const int row = jp * 16 + lr + (gg >> 1) * 8;
                const int ch  = kc * 2 + (gg & 1);
                const uint32_t off = row * 128 + ((ch ^ (row & 7)) << 4);
                uint32_t t0[4], t1[4];
                ldsm_x4(t0, sKh + off);
                ldsm_x4(t1, sKl + off);
                bh[jp*2][0] = t0[0]; bh[jp*2][1] = t0[1];
                bh[jp*2+1][0] = t0[2]; bh[jp*2+1][1] = t0[3];
                bl[jp*2][0] = t1[0]; bl[jp*2][1] = t1[1];
                bl[jp*2+1][0] = t1[2]; bl[jp*2+1][1] = t1[3];
            }
#pragma unroll
            for (int j = 0; j < 8; j++) {
                mma16816(S[j], qfh[kc], bh[j][0], bh[j][1]);
                mma16816(S[j], qfh[kc], bl[j][0], bl[j][1]);
                mma16816(S[j], qfl[kc], bh[j][0], bh[j][1]);
            }
        }

        // ---- scale + causal mask ----
        const int k0 = t * 64;
        const int r0 = q0 + wid * 16 + g, r1 = r0 + 8;
        const bool need_mask = (k0 + 63 > q0 + wid * 16);
#pragma unroll
        for (int j = 0; j < 8; j++) {
#pragma unroll
            for (int e = 0; e < 4; e++) S[j][e] *= scale;
            if (need_mask) {
                const int c0 = k0 + j * 8 + tig * 2, c1 = c0 + 1;
                if (c0 > r0) S[j][0] = -CUDART_INF_F;
                if (c1 > r0) S[j][1] = -CUDART_INF_F;
                if (c0 > r1) S[j][2] = -CUDART_INF_F;
                if (c1 > r1) S[j][3] = -CUDART_INF_F;
            }
        }

        // ---- online softmax (rows g, g+8; quad shfl) ----
        float rx0 = -CUDART_INF_F, rx1 = -CUDART_INF_F;
#pragma unroll
        for (int j = 0; j < 8; j++) {
            rx0 = fmaxf(rx0, fmaxf(S[j][0], S[j][1]));
            rx1 = fmaxf(rx1, fmaxf(S[j][2], S[j][3]));
        }
        rx0 = fmaxf(rx0, __shfl_xor_sync(0xffffffffu, rx0, 1));
        rx0 = fmaxf(rx0, __shfl_xor_sync(0xffffffffu, rx0, 2));
        rx1 = fmaxf(rx1, __shfl_xor_sync(0xffffffffu, rx1, 1));
        rx1 = fmaxf(rx1, __shfl_xor_sync(0xffffffffu, rx1, 2));
        const float nm0 = fmaxf(m0, rx0), nm1 = fmaxf(m1, rx1);
        const float cr0 = __expf(m0 - nm0), cr1 = __expf(m1 - nm1);
        float sm0 = 0.f, sm1 = 0.f;
#pragma unroll
        for (int j = 0; j < 8; j++) {
            S[j][0] = __expf(S[j][0] - nm0); sm0 += S[j][0];
            S[j][1] = __expf(S[j][1] - nm0); sm0 += S[j][1];
            S[j][2] = __expf(S[j][2] - nm1); sm1 += S[j][2];
            S[j][3] = __expf(S[j][3] - nm1); sm1 += S[j][3];
        }
        sm0 += __shfl_xor_sync(0xffffffffu, sm0, 1);
        sm0 += __shfl_xor_sync(0xffffffffu, sm0, 2);
        sm1 += __shfl_xor_sync(0xffffffffu, sm1, 1);
        sm1 += __shfl_xor_sync(0xffffffffu, sm1, 2);
        l0 = l0 * cr0 + sm0; l1 = l1 * cr1 + sm1;
        m0 = nm0; m1 = nm1;
#pragma unroll
        for (int j = 0; j < 8; j++) {
            oacc[j][0] *= cr0; oacc[j][1] *= cr0;
            oacc[j][2] *= cr1; oacc[j][3] *= cr1;
        }

        // ---- O += P V (3-pass hi/lo, V frags via ldmatrix.trans) ----
        const int kvr = (lane & 15);
#pragma unroll
        for (int kc = 0; kc < 4; kc++) {
            uint32_t ph[4], pl[4];
            split_pack(S[2*kc][0],   S[2*kc][1],   ph[0], pl[0]);
            split_pack(S[2*kc][2],   S[2*kc][3],   ph[1], pl[1]);
            split_pack(S[2*kc+1][0], S[2*kc+1][1], ph[2], pl[2]);
            split_pack(S[2*kc+1][2], S[2*kc+1][3], ph[3], pl[3]);
            const int vr = kc * 16 + kvr;
#pragma unroll
            for (int j = 0; j < 8; j++) {
                const uint32_t off = vr * 128 + ((j ^ (vr & 7)) << 4);
                uint32_t vh[2], vl[2];
                ldsm_x2_trans(vh, sVh + off);
                ldsm_x2_trans(vl, sVl + off);
                mma16816(oacc[j], ph, vh[0], vh[1]);
                mma16816(oacc[j], ph, vl[0], vl[1]);
                mma16816(oacc[j], pl, vh[0], vh[1]);
            }
        }
        __syncthreads();
    }

    // ---- write O (bf16 hi/lo) ----
    const float i0 = 1.0f / l0, i1 = 1.0f / l1;
    const int row0 = q0 + wid * 16 + g;
    const size_t gr0 = ((size_t)b * SEQ + row0) * E_DIM;
    const size_t gr1 = gr0 + 8 * E_DIM;
#pragma unroll
    for (int j = 0; j < 8; j++) {
        const int c = h * HDIM + j * 8 + tig * 2;
        __nv_bfloat16 h0, h1, h2, h3, q0b, q1b, q2b, q3b;
        split_bf16(oacc[j][0] * i0, h0, q0b);
        split_bf16(oacc[j][1] * i0, h1, q1b);
        split_bf16(oacc[j][2] * i1, h2, q2b);
        split_bf16(oacc[j][3] * i1, h3, q3b);
        *(__nv_bfloat162*)&ohi[gr0 + c] = {h0, h1};
        *(__nv_bfloat162*)&olo[gr0 + c] = {q0b, q1b};
        *(__nv_bfloat162*)&ohi[gr1 + c] = {h2, h3};
        *(__nv_bfloat162*)&olo[gr1 + c] = {q2b, q3b};
    }
}

// ======================= launch =======================
extern "C" void kernel_launch(void* const* d_in, const int* in_sizes, int n_in,
                              void* d_out, int out_size) {
    const float* x      = (const float*)d_in[0];
    const float* w_in   = (const float*)d_in[1];
    const float* w_out  = (const float*)d_in[2];
    const float* w_fc   = (const float*)d_in[3];
    const float* b_fc   = (const float*)d_in[4];
    const float* w_proj = (const float*)d_in[5];
    const float* b_proj = (const float*)d_in[6];
    float* out = (float*)d_out;

    __nv_bfloat16 *h_hi, *h_lo, *o_hi, *o_lo, *mb_hi, *mb_lo;
    __nv_bfloat16 *wi_hi, *wi_lo, *wo_hi, *wo_lo, *wf_hi, *wf_lo, *wp_hi, *wp_lo;
    float *x2;
    cudaGetSymbolAddress((void**)&h_hi,  g_h_hi);  cudaGetSymbolAddress((void**)&h_lo,  g_h_lo);
    cudaGetSymbolAddress((void**)&o_hi,  g_o_hi);  cudaGetSymbolAddress((void**)&o_lo,  g_o_lo);
    cudaGetSymbolAddress((void**)&x2,    g_x2);
    cudaGetSymbolAddress((void**)&mb_hi, g_mb_hi); cudaGetSymbolAddress((void**)&mb_lo, g_mb_lo);
    cudaGetSymbolAddress((void**)&wi_hi, g_wi_hi); cudaGetSymbolAddress((void**)&wi_lo, g_wi_lo);
    cudaGetSymbolAddress((void**)&wo_hi, g_wo_hi); cudaGetSymbolAddress((void**)&wo_lo, g_wo_lo);
    cudaGetSymbolAddress((void**)&wf_hi, g_wf_hi); cudaGetSymbolAddress((void**)&wf_lo, g_wf_lo);
    cudaGetSymbolAddress((void**)&wp_hi, g_wp_hi); cudaGetSymbolAddress((void**)&wp_lo, g_wp_lo);

    cudaFuncSetAttribute(gemm_tc<1>, cudaFuncAttributeMaxDynamicSharedMemorySize, GEMM_SMEM);
    cudaFuncSetAttribute(gemm_tc<2>, cudaFuncAttributeMaxDynamicSharedMemorySize, GEMM_SMEM);
    cudaFuncSetAttribute(gemm_tc<3>, cudaFuncAttributeMaxDynamicSharedMemorySize, GEMM_SMEM);
    cudaFuncSetAttribute(gemm_tc<4>, cudaFuncAttributeMaxDynamicSharedMemorySize, GEMM_SMEM);
    cudaFuncSetAttribute(attn_mma,   cudaFuncAttributeMaxDynamicSharedMemorySize, ATT_SMEM);

    // weight splits
    cvt_kernel<<<512, 256>>>(w_in,   wi_hi, wi_lo, 3 * E_DIM * E_DIM / 4);
    cvt_kernel<<<512, 256>>>(w_out,  wo_hi, wo_lo, E_DIM * E_DIM / 4);
    cvt_kernel<<<512, 256>>>(w_fc,   wf_hi, wf_lo, 4 * E_DIM * E_DIM / 4);
    cvt_kernel<<<512, 256>>>(w_proj, wp_hi, wp_lo, E_DIM * 4 * E_DIM / 4);

    // h = ln(x) -> bf16 split
    ln_kernel<<<MTOT, 256>>>(x, h_hi, h_lo);
    // qkv = h @ w_in^T -> bf16 hi/lo (into mb buffers)
    gemm_tc<4><<<dim3(3 * E_DIM / 128, MTOT / 128), 256, GEMM_SMEM>>>(
        h_hi, h_lo, wi_hi, wi_lo, nullptr, nullptr, nullptr, mb_hi, mb_lo,
        MTOT, 3 * E_DIM, E_DIM);
    // o = causal_attn(qkv) -> bf16 hi/lo
    attn_mma<<<dim3(SEQ / 128, NHEAD, BATCH), 256, ATT_SMEM>>>(mb_hi, mb_lo, o_hi, o_lo);
    // x2 = x + o @ w_out^T
    gemm_tc<2><<<dim3(E_DIM / 128, MTOT / 128), 256, GEMM_SMEM>>>(
        o_hi, o_lo, wo_hi, wo_lo, nullptr, x, x2, nullptr, nullptr,
        MTOT, E_DIM, E_DIM);
    // h = ln(x2) -> bf16 split
    ln_kernel<<<MTOT, 256>>>(x2, h_hi, h_lo);
    // mb = relu(h @ w_fc^T + b_fc) -> bf16 hi/lo
    gemm_tc<1><<<dim3(4 * E_DIM / 128, MTOT / 128), 256, GEMM_SMEM>>>(
        h_hi, h_lo, wf_hi, wf_lo, b_fc, nullptr, nullptr, mb_hi, mb_lo,
        MTOT, 4 * E_DIM, E_DIM);
    // out = mb @ w_proj^T + b_proj + x2
    gemm_tc<3><<<dim3(E_DIM / 128, MTOT / 128), 256, GEMM_SMEM>>>(
        mb_hi, mb_lo, wp_hi, wp_lo, b_proj, x2, out, nullptr, nullptr,
        MTOT, E_DIM, 4 * E_DIM);
}

// round 5
// speedup vs baseline: 3.3844x; 1.0086x over previous
#include <cuda_runtime.h>
#include <cuda_bf16.h>
#include <math_constants.h>
#include <cstdint>

#define E_DIM 1024
#define BATCH 2
#define SEQ   2048
#define NHEAD 16
#define HDIM  64
#define MTOT  4096   // BATCH*SEQ

// ======================= scratch =======================
__device__ __nv_bfloat16 g_h_hi [MTOT * E_DIM];
__device__ __nv_bfloat16 g_h_lo [MTOT * E_DIM];
__device__ __nv_bfloat16 g_o_hi [MTOT * E_DIM];
__device__ __nv_bfloat16 g_o_lo [MTOT * E_DIM];
__device__ float         g_x2   [MTOT * E_DIM];
__device__ __nv_bfloat16 g_mb_hi[MTOT * 4 * E_DIM];   // reused: qkv hi, then mlp hidden hi
__device__ __nv_bfloat16 g_mb_lo[MTOT * 4 * E_DIM];   // reused: qkv lo, then mlp hidden lo
__device__ __nv_bfloat16 g_wi_hi[3 * E_DIM * E_DIM];
__device__ __nv_bfloat16 g_wi_lo[3 * E_DIM * E_DIM];
__device__ __nv_bfloat16 g_wo_hi[E_DIM * E_DIM];
__device__ __nv_bfloat16 g_wo_lo[E_DIM * E_DIM];
__device__ __nv_bfloat16 g_wf_hi[4 * E_DIM * E_DIM];
__device__ __nv_bfloat16 g_wf_lo[4 * E_DIM * E_DIM];
__device__ __nv_bfloat16 g_wp_hi[E_DIM * 4 * E_DIM];
__device__ __nv_bfloat16 g_wp_lo[E_DIM * 4 * E_DIM];

__device__ __forceinline__ void split_bf16(float x, __nv_bfloat16& h, __nv_bfloat16& l) {
    h = __float2bfloat16_rn(x);
    l = __float2bfloat16_rn(x - __bfloat162float(h));
}
__device__ __forceinline__ void split_pack(float f0, float f1, uint32_t& h, uint32_t& l) {
    __nv_bfloat16 h0, l0, h1, l1;
    split_bf16(f0, h0, l0); split_bf16(f1, h1, l1);
    __nv_bfloat162 hh = {h0, h1}, ll = {l0, l1};
    h = *(uint32_t*)&hh; l = *(uint32_t*)&ll;
}

__device__ __forceinline__ uint32_t smem_u32(const void* p) {
    uint32_t a;
    asm("{ .reg .u64 t; cvta.to.shared.u64 t, %1; cvt.u32.u64 %0, t; }" : "=r"(a) : "l"(p));
    return a;
}
__device__ __forceinline__ void ldsm_x4(uint32_t (&r)[4], uint32_t addr) {
    asm volatile("ldmatrix.sync.aligned.m8n8.x4.shared.b16 {%0,%1,%2,%3}, [%4];"
                 : "=r"(r[0]), "=r"(r[1]), "=r"(r[2]), "=r"(r[3]) : "r"(addr));
}
__device__ __forceinline__ void ldsm_x2_trans(uint32_t (&r)[2], uint32_t addr) {
    asm volatile("ldmatrix.sync.aligned.m8n8.x2.trans.shared.b16 {%0,%1}, [%2];"
                 : "=r"(r[0]), "=r"(r[1]) : "r"(addr));
}
__device__ __forceinline__ void mma16816(float (&d)[4], const uint32_t (&a)[4],
                                         uint32_t b0, uint32_t b1) {
    asm volatile("mma.sync.aligned.m16n8k16.row.col.f32.bf16.bf16.f32 "
                 "{%0,%1,%2,%3}, {%4,%5,%6,%7}, {%8,%9}, {%0,%1,%2,%3};"
                 : "+f"(d[0]), "+f"(d[1]), "+f"(d[2]), "+f"(d[3])
                 : "r"(a[0]), "r"(a[1]), "r"(a[2]), "r"(a[3]), "r"(b0), "r"(b1));
}
__device__ __forceinline__ void cp_async16(uint32_t saddr, const void* gaddr) {
    asm volatile("cp.async.cg.shared.global [%0], [%1], 16;" :: "r"(saddr), "l"(gaddr));
}
__device__ __forceinline__ void cp_commit() {
    asm volatile("cp.async.commit_group;" ::: "memory");
}
template<int N> __device__ __forceinline__ void cp_wait() {
    asm volatile("cp.async.wait_group %0;" :: "n"(N) : "memory");
}

// ======================= fused weight convert =======================
// one launch converts all four weight matrices (regions in float4 units)
#define WI_N4 (3 * E_DIM * E_DIM / 4)
#define WO_N4 (E_DIM * E_DIM / 4)
#define WF_N4 (4 * E_DIM * E_DIM / 4)
#define WP_N4 (4 * E_DIM * E_DIM / 4)
#define CVT_TOT (WI_N4 + WO_N4 + WF_N4 + WP_N4)

__global__ __launch_bounds__(256) void cvt_all(
    const float* __restrict__ w_in, const float* __restrict__ w_out,
    const float* __restrict__ w_fc, const float* __restrict__ w_proj,
    __nv_bfloat16* __restrict__ wi_hi, __nv_bfloat16* __restrict__ wi_lo,
    __nv_bfloat16* __restrict__ wo_hi, __nv_bfloat16* __restrict__ wo_lo,
    __nv_bfloat16* __restrict__ wf_hi, __nv_bfloat16* __restrict__ wf_lo,
    __nv_bfloat16* __restrict__ wp_hi, __nv_bfloat16* __restrict__ wp_lo)
{
    const int stride = gridDim.x * blockDim.x;
    for (int i = blockIdx.x * blockDim.x + threadIdx.x; i < CVT_TOT; i += stride) {
        const float* src; __nv_bfloat16 *hi, *lo; int j = i;
        if (j < WI_N4)                { src = w_in;   hi = wi_hi; lo = wi_lo; }
        else if ((j -= WI_N4) < WO_N4){ src = w_out;  hi = wo_hi; lo = wo_lo; }
        else if ((j -= WO_N4) < WF_N4){ src = w_fc;   hi = wf_hi; lo = wf_lo; }
        else { j -= WF_N4;              src = w_proj; hi = wp_hi; lo = wp_lo; }
        float4 v = ((const float4*)src)[j];
        __nv_bfloat16 h0, h1, h2, h3, l0, l1, l2, l3;
        split_bf16(v.x, h0, l0); split_bf16(v.y, h1, l1);
        split_bf16(v.z, h2, l2); split_bf16(v.w, h3, l3);
        __nv_bfloat162* ph = (__nv_bfloat162*)&hi[(size_t)j * 4];
        __nv_bfloat162* pl = (__nv_bfloat162*)&lo[(size_t)j * 4];
        ph[0] = {h0, h1}; ph[1] = {h2, h3};
        pl[0] = {l0, l1}; pl[1] = {l2, l3};
    }
}

// ======================= layernorm (emits hi/lo bf16) =======================
__global__ __launch_bounds__(256) void ln_kernel(const float* __restrict__ x,
                                                 __nv_bfloat16* __restrict__ yhi,
                                                 __nv_bfloat16* __restrict__ ylo) {
    __shared__ float rs[8], rq[8];
    const int row = blockIdx.x;
    const int tid = threadIdx.x;
    float4 v = ((const float4*)(x + (size_t)row * E_DIM))[tid];
    float s  = v.x + v.y + v.z + v.w;
    float sq = v.x*v.x + v.y*v.y + v.z*v.z + v.w*v.w;
#pragma unroll
    for (int o = 16; o; o >>= 1) {
        s  += __shfl_xor_sync(0xffffffffu, s,  o);
        sq += __shfl_xor_sync(0xffffffffu, sq, o);
    }
    if ((tid & 31) == 0) { rs[tid >> 5] = s; rq[tid >> 5] = sq; }
    __syncthreads();
    if (tid < 32) {
        s  = (tid < 8) ? rs[tid] : 0.f;
        sq = (tid < 8) ? rq[tid] : 0.f;
#pragma unroll
        for (int o = 4; o; o >>= 1) {
            s  += __shfl_xor_sync(0xffffffffu, s,  o);
            sq += __shfl_xor_sync(0xffffffffu, sq, o);
        }
        if (tid == 0) { rs[0] = s; rq[0] = sq; }
    }
    __syncthreads();
    const float mean = rs[0] * (1.0f / E_DIM);
    const float var  = rq[0] * (1.0f / E_DIM) - mean * mean;
    const float rstd = rsqrtf(var + 1e-5f);
    float y0 = (v.x - mean) * rstd, y1 = (v.y - mean) * rstd;
    float y2 = (v.z - mean) * rstd, y3 = (v.w - mean) * rstd;
    __nv_bfloat16 h0, h1, h2, h3, l0, l1, l2, l3;
    split_bf16(y0, h0, l0); split_bf16(y1, h1, l1);
    split_bf16(y2, h2, l2); split_bf16(y3, h3, l3);
    __nv_bfloat162* ph = (__nv_bfloat162*)&yhi[(size_t)row * E_DIM + tid * 4];
    __nv_bfloat162* pl = (__nv_bfloat162*)&ylo[(size_t)row * E_DIM + tid * 4];
    ph[0] = {h0, h1}; ph[1] = {h2, h3};
    pl[0] = {l0, l1}; pl[1] = {l2, l3};
}

// ======================= tensor-core GEMM (mma.sync bf16, hi/lo x3) =======================
// C[M,N] = A[M,K] * B[N,K]^T  -- 3-stage cp.async pipeline, one barrier per chunk
// MODE 1: relu(+bias)->bf16 hi/lo | 2: +res fp32 | 3: +bias+res fp32 | 4: bf16 hi/lo
#define TILE_BYTES  16384               // 128 rows x 128 bytes (64 bf16)
#define STAGE_BYTES (4 * TILE_BYTES)    // Ah, Al, Bh, Bl
#define GEMM_STAGES 3
#define GEMM_SMEM   (GEMM_STAGES * STAGE_BYTES)   // 192 KB

template<int MODE>
__global__ __launch_bounds__(256) void gemm_tc(
    const __nv_bfloat16* __restrict__ Ah, const __nv_bfloat16* __restrict__ Al,
    const __nv_bfloat16* __restrict__ Bh, const __nv_bfloat16* __restrict__ Bl,
    const float* __restrict__ bias, const float* __restrict__ res,
    float* __restrict__ Cf, __nv_bfloat16* __restrict__ Chi,
    __nv_bfloat16* __restrict__ Clo, int M, int N, int K)
{
    extern __shared__ char smem[];
    const uint32_t sbase = smem_u32(smem);
    const int tid  = threadIdx.x;
    const int wid  = tid >> 5;
    const int lane = tid & 31;
    const int row0 = blockIdx.y * 128;
    const int col0 = blockIdx.x * 128;
    const int wm = (wid & 1) * 64;
    const int wn = (wid >> 1) * 32;

    float acc[4][4][4];
#pragma unroll
    for (int i = 0; i < 4; i++)
#pragma unroll
        for (int j = 0; j < 4; j++)
#pragma unroll
            for (int k = 0; k < 4; k++) acc[i][j][k] = 0.f;

    const int NC = K >> 6;

    auto issue_stage = [&](int c) {
        const uint32_t st = sbase + (c % GEMM_STAGES) * STAGE_BYTES;
        const int k0 = c << 6;
#pragma unroll
        for (int t = 0; t < 4; t++) {
            const __nv_bfloat16* g = (t == 0) ? Ah : (t == 1) ? Al : (t == 2) ? Bh : Bl;
            const int rbase = (t < 2) ? row0 : col0;
            const uint32_t tb = st + t * TILE_BYTES;
#pragma unroll
            for (int i = 0; i < 4; i++) {
                const int idx = tid + i * 256;
                const int r = idx >> 3, cc = idx & 7;
                cp_async16(tb + r * 128 + ((cc ^ (r & 7)) << 4),
                           g + (size_t)(rbase + r) * K + k0 + cc * 8);
            }
        }
        cp_commit();
    };

    issue_stage(0);
    if (NC > 1) issue_stage(1);

    for (int c = 0; c < NC; c++) {
        if (c < NC - 1) cp_wait<1>();
        else            cp_wait<0>();
        __syncthreads();
        if (c + 2 < NC) issue_stage(c + 2);

        const uint32_t st  = sbase + (c % GEMM_STAGES) * STAGE_BYTES;
        const uint32_t sAh = st;
        const uint32_t sAl = st + TILE_BYTES;
        const uint32_t sBh = st + 2 * TILE_BYTES;
        const uint32_t sBl = st + 3 * TILE_BYTES;
        const int g  = lane >> 3;
        const int lr = lane & 7;

#pragma unroll
        for (int ks = 0; ks < 4; ks++) {
            const int kc0 = ks * 2;
            uint32_t ah[4][4], al[4][4], bh[4][2], bl[4][2];
#pragma unroll
            for (int mt = 0; mt < 4; mt++) {
                const int row = wm + mt * 16 + lr + (g & 1) * 8;
                const int ch  = kc0 + (g >> 1);
                const uint32_t off = row * 128 + ((ch ^ (row & 7)) << 4);
                ldsm_x4(ah[mt], sAh + off);
                ldsm_x4(al[mt], sAl + off);
            }
#pragma unroll
            for (int np = 0; np < 2; np++) {
                const int row = wn + np * 16 + lr + (g >> 1) * 8;
                const int ch  = kc0 + (g & 1);
                const uint32_t off = row * 128 + ((ch ^ (row & 7)) << 4);
                uint32_t t0[4], t1[4];
                ldsm_x4(t0, sBh + off);
                ldsm_x4(t1, sBl + off);
                bh[np*2][0] = t0[0]; bh[np*2][1] = t0[1];
                bh[np*2+1][0] = t0[2]; bh[np*2+1][1] = t0[3];
                bl[np*2][0] = t1[0]; bl[np*2][1] = t1[1];
                bl[np*2+1][0] = t1[2]; bl[np*2+1][1] = t1[3];
            }
#pragma unroll
            for (int mt = 0; mt < 4; mt++)
#pragma unroll
                for (int nt = 0; nt < 4; nt++) {
                    mma16816(acc[mt][nt], ah[mt], bh[nt][0], bh[nt][1]);
                    mma16816(acc[mt][nt], ah[mt], bl[nt][0], bl[nt][1]);
                    mma16816(acc[mt][nt], al[mt], bh[nt][0], bh[nt][1]);
                }
        }
    }

#pragma unroll
    for (int mt = 0; mt < 4; mt++) {
#pragma unroll
        for (int nt = 0; nt < 4; nt++) {
            const int r0 = row0 + wm + mt * 16 + (lane >> 2);
            const int r1 = r0 + 8;
            const int cc = col0 + wn + nt * 8 + (lane & 3) * 2;
            float v0 = acc[mt][nt][0], v1 = acc[mt][nt][1];
            float v2 = acc[mt][nt][2], v3 = acc[mt][nt][3];
            if (MODE == 1 || MODE == 3) {
                const float b0 = bias[cc], b1 = bias[cc + 1];
                v0 += b0; v1 += b1; v2 += b0; v3 += b1;
            }
            if (MODE == 1) {
                v0 = fmaxf(v0, 0.f); v1 = fmaxf(v1, 0.f);
                v2 = fmaxf(v2, 0.f); v3 = fmaxf(v3, 0.f);
            }
            if (MODE == 2 || MODE == 3) {
                float2 ra = *(const float2*)&res[(size_t)r0 * N + cc];
                float2 rb = *(const float2*)&res[(size_t)r1 * N + cc];
                v0 += ra.x; v1 += ra.y; v2 += rb.x; v3 += rb.y;
            }
            if (MODE == 1 || MODE == 4) {
                __nv_bfloat16 h0, h1, h2, h3, l0, l1, l2, l3;
                split_bf16(v0, h0, l0); split_bf16(v1, h1, l1);
                split_bf16(v2, h2, l2); split_bf16(v3, h3, l3);
                *(__nv_bfloat162*)&Chi[(size_t)r0 * N + cc] = {h0, h1};
                *(__nv_bfloat162*)&Chi[(size_t)r1 * N + cc] = {h2, h3};
                *(__nv_bfloat162*)&Clo[(size_t)r0 * N + cc] = {l0, l1};
                *(__nv_bfloat162*)&Clo[(size_t)r1 * N + cc] = {l2, l3};
            } else {
                *(float2*)&Cf[(size_t)r0 * N + cc] = {v0, v1};
                *(float2*)&Cf[(size_t)r1 * N + cc] = {v2, v3};
            }
        }
    }
}

// ======================= MMA causal flash attention =======================
// CTA: 128 q rows (8 warps x 16), KV tiles of 64, double-buffered.
// smem: Qh 16K | Ql 16K | stage0 {Kh,Kl,Vh,Vl 8K each} | stage1 {...} = 96 KB
#define ATT_SMEM 98304

__global__ __launch_bounds__(256) void attn_mma(
    const __nv_bfloat16* __restrict__ qkvh, const __nv_bfloat16* __restrict__ qkvl,
    __nv_bfloat16* __restrict__ ohi, __nv_bfloat16* __restrict__ olo)
{
    extern __shared__ char smem[];
    const uint32_t sb = smem_u32(smem);
    const int tid = threadIdx.x, wid = tid >> 5, lane = tid & 31;
    const int qb = (int)gridDim.x - 1 - (int)blockIdx.x;   // longest blocks first
    const int q0 = qb * 128;
    const int h  = blockIdx.y, b = blockIdx.z;
    const int LD = 3 * E_DIM;
    const size_t base = (size_t)b * SEQ * LD + (size_t)h * HDIM;

    const uint32_t sQh = sb, sQl = sb + 16384;

#pragma unroll
    for (int i = 0; i < 4; i++) {
        const int idx = tid + i * 256;
        const int r = idx >> 3, cc = idx & 7;
        const uint32_t soff = r * 128 + ((cc ^ (r & 7)) << 4);
        cp_async16(sQh + soff, qkvh + base + (size_t)(q0 + r) * LD + cc * 8);
        cp_async16(sQl + soff, qkvl + base + (size_t)(q0 + r) * LD + cc * 8);
    }
    auto issue_kv = [&](int t) {
        const uint32_t st = sb + 32768 + (t & 1) * 32768;
        const int k0 = t * 64;
#pragma unroll
        for (int i = 0; i < 2; i++) {
            const int idx = tid + i * 256;
            const int r = idx >> 3, cc = idx & 7;
            const uint32_t soff = r * 128 + ((cc ^ (r & 7)) << 4);
            const size_t gk = base + E_DIM     + (size_t)(k0 + r) * LD + cc * 8;
            const size_t gv = base + 2 * E_DIM + (size_t)(k0 + r) * LD + cc * 8;
            cp_async16(st +         soff, qkvh + gk);
            cp_async16(st + 8192  + soff, qkvl + gk);
            cp_async16(st + 16384 + soff, qkvh + gv);
            cp_async16(st + 24576 + soff, qkvl + gv);
        }
        cp_commit();
    };
    issue_kv(0);

    const int ntiles = (q0 >> 6) + 2;
    const int g = lane >> 2, tig = lane & 3;
    const int lr = lane & 7, gg = lane >> 3;

    float oacc[8][4];
#pragma unroll
    for (int j = 0; j < 8; j++)
#pragma unroll
        for (int e = 0; e < 4; e++) oacc[j][e] = 0.f;
    float m0 = -CUDART_INF_F, m1 = -CUDART_INF_F, l0 = 0.f, l1 = 0.f;
    uint32_t qfh[4][4], qfl[4][4];
    const float scale = 0.125f;

    for (int t = 0; t < ntiles; t++) {
        if (t + 1 < ntiles) { issue_kv(t + 1); cp_wait<1>(); }
        else                { cp_wait<0>(); }
        __syncthreads();
        if (t == 0) {
            const int row = wid * 16 + lr + (gg & 1) * 8;
#pragma unroll
            for (int kc = 0; kc < 4; kc++) {
                const int ch = kc * 2 + (gg >> 1);
                const uint32_t off = row * 128 + ((ch ^ (row & 7)) << 4);
                ldsm_x4(qfh[kc], sQh + off);
                ldsm_x4(qfl[kc], sQl + off);
            }
        }
        const uint32_t sKh = sb + 32768 + (t & 1) * 32768;
        const uint32_t sKl = sKh + 8192;
        const uint32_t sVh = sKh + 16384;
        const uint32_t sVl = sKh + 24576;

        // ---- S = Q K^T (3-pass hi/lo) ----
        float S[8][4];
#pragma unroll
        for (int j = 0; j < 8; j++)
#pragma unroll
            for (int e = 0; e < 4; e++) S[j][e] = 0.f;
#pragma unroll
        for (int kc = 0; kc < 4; kc++) {
            uint32_t bh[8][2], bl[8][2];
#pragma unroll
            for (int jp = 0; jp < 4; jp++) {
                const int row = jp * 16 + lr + (gg >> 1) * 8;
                const int ch  = kc * 2 + (gg & 1);
                const uint32_t off = row * 128 + ((ch ^ (row & 7)) << 4);
                uint32_t t0[4], t1[4];
                ldsm_x4(t0, sKh + off);
                ldsm_x4(t1, sKl + off);
                bh[jp*2][0] = t0[0]; bh[jp*2][1] = t0[1];
                bh[jp*2+1][0] = t0[2]; bh[jp*2+1][1] = t0[3];
                bl[jp*2][0] = t1[0]; bl[jp*2][1] = t1[1];
                bl[jp*2+1][0] = t1[2]; bl[jp*2+1][1] = t1[3];
            }
#pragma unroll
            for (int j = 0; j < 8; j++) {
                mma16816(S[j], qfh[kc], bh[j][0], bh[j][1]);
                mma16816(S[j], qfh[kc], bl[j][0], bl[j][1]);
                mma16816(S[j], qfl[kc], bh[j][0], bh[j][1]);
            }
        }

        // ---- scale + causal mask ----
        const int k0 = t * 64;
        const int r0 = q0 + wid * 16 + g, r1 = r0 + 8;
        const bool need_mask = (k0 + 63 > q0 + wid * 16);
#pragma unroll
        for (int j = 0; j < 8; j++) {
#pragma unroll
            for (int e = 0; e < 4; e++) S[j][e] *= scale;
            if (need_mask) {
                const int c0 = k0 + j * 8 + tig * 2, c1 = c0 + 1;
                if (c0 > r0) S[j][0] = -CUDART_INF_F;
                if (c1 > r0) S[j][1] = -CUDART_INF_F;
                if (c0 > r1) S[j][2] = -CUDART_INF_F;
                if (c1 > r1) S[j][3] = -CUDART_INF_F;
            }
        }

        // ---- online softmax ----
        float rx0 = -CUDART_INF_F, rx1 = -CUDART_INF_F;
#pragma unroll
        for (int j = 0; j < 8; j++) {
            rx0 = fmaxf(rx0, fmaxf(S[j][0], S[j][1]));
            rx1 = fmaxf(rx1, fmaxf(S[j][2], S[j][3]));
        }
        rx0 = fmaxf(rx0, __shfl_xor_sync(0xffffffffu, rx0, 1));
        rx0 = fmaxf(rx0, __shfl_xor_sync(0xffffffffu, rx0, 2));
        rx1 = fmaxf(rx1, __shfl_xor_sync(0xffffffffu, rx1, 1));
        rx1 = fmaxf(rx1, __shfl_xor_sync(0xffffffffu, rx1, 2));
        const float nm0 = fmaxf(m0, rx0), nm1 = fmaxf(m1, rx1);
        const float cr0 = __expf(m0 - nm0), cr1 = __expf(m1 - nm1);
        float sm0 = 0.f, sm1 = 0.f;
#pragma unroll
        for (int j = 0; j < 8; j++) {
            S[j][0] = __expf(S[j][0] - nm0); sm0 += S[j][0];
            S[j][1] = __expf(S[j][1] - nm0); sm0 += S[j][1];
            S[j][2] = __expf(S[j][2] - nm1); sm1 += S[j][2];
            S[j][3] = __expf(S[j][3] - nm1); sm1 += S[j][3];
        }
        sm0 += __shfl_xor_sync(0xffffffffu, sm0, 1);
        sm0 += __shfl_xor_sync(0xffffffffu, sm0, 2);
        sm1 += __shfl_xor_sync(0xffffffffu, sm1, 1);
        sm1 += __shfl_xor_sync(0xffffffffu, sm1, 2);
        l0 = l0 * cr0 + sm0; l1 = l1 * cr1 + sm1;
        m0 = nm0; m1 = nm1;
#pragma unroll
        for (int j = 0; j < 8; j++) {
            oacc[j][0] *= cr0; oacc[j][1] *= cr0;
            oacc[j][2] *= cr1; oacc[j][3] *= cr1;
        }

        // ---- O += P V (3-pass hi/lo) ----
        const int kvr = (lane & 15);
#pragma unroll
        for (int kc = 0; kc < 4; kc++) {
            uint32_t ph[4], pl[4];
            split_pack(S[2*kc][0],   S[2*kc][1],   ph[0], pl[0]);
            split_pack(S[2*kc][2],   S[2*kc][3],   ph[1], pl[1]);
            split_pack(S[2*kc+1][0], S[2*kc+1][1], ph[2], pl[2]);
            split_pack(S[2*kc+1][2], S[2*kc+1][3], ph[3], pl[3]);
            const int vr = kc * 16 + kvr;
#pragma unroll
            for (int j = 0; j < 8; j++) {
                const uint32_t off = vr * 128 + ((j ^ (vr & 7)) << 4);
                uint32_t vh[2], vl[2];
                ldsm_x2_trans(vh, sVh + off);
                ldsm_x2_trans(vl, sVl + off);
                mma16816(oacc[j], ph, vh[0], vh[1]);
                mma16816(oacc[j], ph, vl[0], vl[1]);
                mma16816(oacc[j], pl, vh[0], vh[1]);
            }
        }
        __syncthreads();
    }

    // ---- write O (bf16 hi/lo) ----
    const float i0 = 1.0f / l0, i1 = 1.0f / l1;
    const int row0 = q0 + wid * 16 + g;
    const size_t gr0 = ((size_t)b * SEQ + row0) * E_DIM;
    const size_t gr1 = gr0 + 8 * E_DIM;
#pragma unroll
    for (int j = 0; j < 8; j++) {
        const int c = h * HDIM + j * 8 + tig * 2;
        __nv_bfloat16 h0, h1, h2, h3, q0b, q1b, q2b, q3b;
        split_bf16(oacc[j][0] * i0, h0, q0b);
        split_bf16(oacc[j][1] * i0, h1, q1b);
        split_bf16(oacc[j][2] * i1, h2, q2b);
        split_bf16(oacc[j][3] * i1, h3, q3b);
        *(__nv_bfloat162*)&ohi[gr0 + c] = {h0, h1};
        *(__nv_bfloat162*)&olo[gr0 + c] = {q0b, q1b};
        *(__nv_bfloat162*)&ohi[gr1 + c] = {h2, h3};
        *(__nv_bfloat162*)&olo[gr1 + c] = {q2b, q3b};
    }
}

// ======================= launch =======================
extern "C" void kernel_launch(void* const* d_in, const int* in_sizes, int n_in,
                              void* d_out, int out_size) {
    const float* x      = (const float*)d_in[0];
    const float* w_in   = (const float*)d_in[1];
    const float* w_out  = (const float*)d_in[2];
    const float* w_fc   = (const float*)d_in[3];
    const float* b_fc   = (const float*)d_in[4];
    const float* w_proj = (const float*)d_in[5];
    const float* b_proj = (const float*)d_in[6];
    float* out = (float*)d_out;

    __nv_bfloat16 *h_hi, *h_lo, *o_hi, *o_lo, *mb_hi, *mb_lo;
    __nv_bfloat16 *wi_hi, *wi_lo, *wo_hi, *wo_lo, *wf_hi, *wf_lo, *wp_hi, *wp_lo;
    float *x2;
    cudaGetSymbolAddress((void**)&h_hi,  g_h_hi);  cudaGetSymbolAddress((void**)&h_lo,  g_h_lo);
    cudaGetSymbolAddress((void**)&o_hi,  g_o_hi);  cudaGetSymbolAddress((void**)&o_lo,  g_o_lo);
    cudaGetSymbolAddress((void**)&x2,    g_x2);
    cudaGetSymbolAddress((void**)&mb_hi, g_mb_hi); cudaGetSymbolAddress((void**)&mb_lo, g_mb_lo);
    cudaGetSymbolAddress((void**)&wi_hi, g_wi_hi); cudaGetSymbolAddress((void**)&wi_lo, g_wi_lo);
    cudaGetSymbolAddress((void**)&wo_hi, g_wo_hi); cudaGetSymbolAddress((void**)&wo_lo, g_wo_lo);
    cudaGetSymbolAddress((void**)&wf_hi, g_wf_hi); cudaGetSymbolAddress((void**)&wf_lo, g_wf_lo);
    cudaGetSymbolAddress((void**)&wp_hi, g_wp_hi); cudaGetSymbolAddress((void**)&wp_lo, g_wp_lo);

    cudaFuncSetAttribute(gemm_tc<1>, cudaFuncAttributeMaxDynamicSharedMemorySize, GEMM_SMEM);
    cudaFuncSetAttribute(gemm_tc<2>, cudaFuncAttributeMaxDynamicSharedMemorySize, GEMM_SMEM);
    cudaFuncSetAttribute(gemm_tc<3>, cudaFuncAttributeMaxDynamicSharedMemorySize, GEMM_SMEM);
    cudaFuncSetAttribute(gemm_tc<4>, cudaFuncAttributeMaxDynamicSharedMemorySize, GEMM_SMEM);
    cudaFuncSetAttribute(attn_mma,   cudaFuncAttributeMaxDynamicSharedMemorySize, ATT_SMEM);

    // all weight splits in one launch
    cvt_all<<<2048, 256>>>(w_in, w_out, w_fc, w_proj,
                           wi_hi, wi_lo, wo_hi, wo_lo, wf_hi, wf_lo, wp_hi, wp_lo);

    // h = ln(x) -> bf16 split
    ln_kernel<<<MTOT, 256>>>(x, h_hi, h_lo);
    // qkv = h @ w_in^T -> bf16 hi/lo (into mb buffers)
    gemm_tc<4><<<dim3(3 * E_DIM / 128, MTOT / 128), 256, GEMM_SMEM>>>(
        h_hi, h_lo, wi_hi, wi_lo, nullptr, nullptr, nullptr, mb_hi, mb_lo,
        MTOT, 3 * E_DIM, E_DIM);
    // o = causal_attn(qkv) -> bf16 hi/lo
    attn_mma<<<dim3(SEQ / 128, NHEAD, BATCH), 256, ATT_SMEM>>>(mb_hi, mb_lo, o_hi, o_lo);
    // x2 = x + o @ w_out^T
    gemm_tc<2><<<dim3(E_DIM / 128, MTOT / 128), 256, GEMM_SMEM>>>(
        o_hi, o_lo, wo_hi, wo_lo, nullptr, x, x2, nullptr, nullptr,
        MTOT, E_DIM, E_DIM);
    // h = ln(x2) -> bf16 split
    ln_kernel<<<MTOT, 256>>>(x2, h_hi, h_lo);
    // mb = relu(h @ w_fc^T + b_fc) -> bf16 hi/lo
    gemm_tc<1><<<dim3(4 * E_DIM / 128, MTOT / 128), 256, GEMM_SMEM>>>(
        h_hi, h_lo, wf_hi, wf_lo, b_fc, nullptr, nullptr, mb_hi, mb_lo,
        MTOT, 4 * E_DIM, E_DIM);
    // out = mb @ w_proj^T + b_proj + x2
    gemm_tc<3><<<dim3(E_DIM / 128, MTOT / 128), 256, GEMM_SMEM>>>(
        mb_hi, mb_lo, wp_hi, wp_lo, b_proj, x2, out, nullptr, nullptr,
        MTOT, E_DIM, 4 * E_DIM);
}